// round 1
// baseline (speedup 1.0000x reference)
#include <cuda_runtime.h>
#include <math.h>

// Problem sizes (fixed)
#define BB   2
#define SS   2048
#define DD   512
#define WW   64          // attention window
#define MR   (BB*SS)     // 4096 rows

// Scratch (device globals — no allocation allowed)
__device__ float g_q[MR*DD];
__device__ float g_k[MR*DD];
__device__ float g_v[MR*DD];
__device__ float g_r[MR*DD];
__device__ float g_att[MR*DD];
__device__ float g_proj[MR*DD];

// ---------------------------------------------------------------------------
// Tiled SGEMM body: C[4096,512] = A[4096,512] @ W[512,512] + bias
// BM=BN=128, BK=16, 256 threads, 8x8 per thread.
// ---------------------------------------------------------------------------
#define BM 128
#define BN 128
#define BK 16

__device__ __forceinline__ void gemm_body(const float* __restrict__ A,
                                          const float* __restrict__ W,
                                          const float* __restrict__ bias,
                                          float* __restrict__ C)
{
    __shared__ float As[BK][BM + 4];   // padded to reduce STS conflicts
    __shared__ float Bs[BK][BN];

    const int tid = threadIdx.x;
    const int m0  = blockIdx.y * BM;
    const int n0  = blockIdx.x * BN;

    const int tm = (tid >> 4) * 8;     // 0..120
    const int tn = (tid & 15) * 8;     // 0..120

    // A-tile load mapping: float4 id f in {tid, tid+256}: row=f/4, colgrp=(f%4)*4
    const int ar = tid >> 2;           // 0..63  (second load: +64)
    const int ac = (tid & 3) * 4;      // 0,4,8,12
    // B-tile: f: krow=f/32 (second: +8), col=(f%32)*4
    const int br = tid >> 5;           // 0..7
    const int bc = (tid & 31) * 4;     // 0..124

    float acc[8][8];
#pragma unroll
    for (int i = 0; i < 8; i++)
#pragma unroll
        for (int j = 0; j < 8; j++) acc[i][j] = 0.f;

    for (int k0 = 0; k0 < DD; k0 += BK) {
        float4 a0 = *(const float4*)&A[(m0 + ar)      * DD + k0 + ac];
        float4 a1 = *(const float4*)&A[(m0 + ar + 64) * DD + k0 + ac];
        float4 b0 = *(const float4*)&W[(k0 + br)      * DD + n0 + bc];
        float4 b1 = *(const float4*)&W[(k0 + br + 8)  * DD + n0 + bc];

        __syncthreads();
        As[ac + 0][ar] = a0.x; As[ac + 1][ar] = a0.y;
        As[ac + 2][ar] = a0.z; As[ac + 3][ar] = a0.w;
        As[ac + 0][ar + 64] = a1.x; As[ac + 1][ar + 64] = a1.y;
        As[ac + 2][ar + 64] = a1.z; As[ac + 3][ar + 64] = a1.w;
        *(float4*)&Bs[br][bc]     = b0;
        *(float4*)&Bs[br + 8][bc] = b1;
        __syncthreads();

#pragma unroll
        for (int kk = 0; kk < BK; kk++) {
            float a[8], b[8];
            *(float4*)&a[0] = *(const float4*)&As[kk][tm];
            *(float4*)&a[4] = *(const float4*)&As[kk][tm + 4];
            *(float4*)&b[0] = *(const float4*)&Bs[kk][tn];
            *(float4*)&b[4] = *(const float4*)&Bs[kk][tn + 4];
#pragma unroll
            for (int i = 0; i < 8; i++)
#pragma unroll
                for (int j = 0; j < 8; j++)
                    acc[i][j] += a[i] * b[j];
        }
    }

    float bj[8];
    *(float4*)&bj[0] = *(const float4*)&bias[n0 + tn];
    *(float4*)&bj[4] = *(const float4*)&bias[n0 + tn + 4];
#pragma unroll
    for (int i = 0; i < 8; i++) {
        float4 v0 = make_float4(acc[i][0] + bj[0], acc[i][1] + bj[1],
                                acc[i][2] + bj[2], acc[i][3] + bj[3]);
        float4 v1 = make_float4(acc[i][4] + bj[4], acc[i][5] + bj[5],
                                acc[i][6] + bj[6], acc[i][7] + bj[7]);
        *(float4*)&C[(m0 + tm + i) * DD + n0 + tn]     = v0;
        *(float4*)&C[(m0 + tm + i) * DD + n0 + tn + 4] = v1;
    }
}

// Fused Q/K/V/R projections (blockIdx.z selects the weight set)
__global__ void __launch_bounds__(256, 2) k_qkvr(
    const float* __restrict__ x,
    const float* W0, const float* b0,
    const float* W1, const float* b1,
    const float* W2, const float* b2,
    const float* W3, const float* b3)
{
    const float* W; const float* bias; float* C;
    switch (blockIdx.z) {
        case 0:  W = W0; bias = b0; C = g_q; break;
        case 1:  W = W1; bias = b1; C = g_k; break;
        case 2:  W = W2; bias = b2; C = g_v; break;
        default: W = W3; bias = b3; C = g_r; break;
    }
    gemm_body(x, W, bias, C);
}

// Output projection: g_proj = g_att @ Wo + bo
__global__ void __launch_bounds__(256, 2) k_proj(
    const float* __restrict__ Wo, const float* __restrict__ bo)
{
    gemm_body(g_att, Wo, bo, g_proj);
}

// ---------------------------------------------------------------------------
// Local windowed attention: one warp per query, 8 warps per block.
// ---------------------------------------------------------------------------
__global__ void __launch_bounds__(256) k_attn()
{
    const int warp = threadIdx.x >> 5;
    const int lane = threadIdx.x & 31;
    const int gq   = blockIdx.x * 8 + warp;     // global query row 0..4095
    const int b    = gq / SS;
    const int s    = gq - b * SS;
    const int base = b * SS;

    const float* qrow = g_q + gq * DD;
    float qreg[16];
#pragma unroll
    for (int i = 0; i < 16; i++) qreg[i] = qrow[lane + 32 * i];

    __shared__ float sh[8][WW];
    const int j0 = s - (WW - 1);
    const float scale = 0.044194173824159216f;  // 1/sqrt(512)

    // scores
    for (int w = 0; w < WW; w++) {
        const int j = j0 + w;
        float part = 0.f;
        if (j >= 0) {
            const float* krow = g_k + (base + j) * DD;
#pragma unroll
            for (int i = 0; i < 16; i++) part += qreg[i] * krow[lane + 32 * i];
        }
#pragma unroll
        for (int off = 16; off; off >>= 1)
            part += __shfl_down_sync(0xffffffffu, part, off);
        if (lane == 0) sh[warp][w] = (j >= 0) ? part * scale : -1e9f;
    }
    __syncwarp();

    // softmax over 64 (2 scores per lane)
    float s0 = sh[warp][lane], s1 = sh[warp][lane + 32];
    float mx = fmaxf(s0, s1);
#pragma unroll
    for (int off = 16; off; off >>= 1)
        mx = fmaxf(mx, __shfl_xor_sync(0xffffffffu, mx, off));
    float e0 = expf(s0 - mx), e1 = expf(s1 - mx);
    float sum = e0 + e1;
#pragma unroll
    for (int off = 16; off; off >>= 1)
        sum += __shfl_xor_sync(0xffffffffu, sum, off);
    const float inv = 1.0f / sum;
    sh[warp][lane]      = e0 * inv;
    sh[warp][lane + 32] = e1 * inv;
    __syncwarp();

    // weighted sum of V
    float acc[16];
#pragma unroll
    for (int i = 0; i < 16; i++) acc[i] = 0.f;
    for (int w = 0; w < WW; w++) {
        const int j = j0 + w;
        if (j < 0) continue;
        const float p = sh[warp][w];
        const float* vrow = g_v + (base + j) * DD;
#pragma unroll
        for (int i = 0; i < 16; i++) acc[i] += p * vrow[lane + 32 * i];
    }
    float* orow = g_att + gq * DD;
#pragma unroll
    for (int i = 0; i < 16; i++) orow[lane + 32 * i] = acc[i];
}

// ---------------------------------------------------------------------------
// Dual LayerNorm + add + exact GELU. One block (256 threads) per row.
// ---------------------------------------------------------------------------
__global__ void __launch_bounds__(256) k_ln_gelu(
    const float* __restrict__ gamma, const float* __restrict__ beta,
    float* __restrict__ out)
{
    const int row = blockIdx.x;
    const int t   = threadIdx.x;
    const float* p = g_proj + row * DD;
    const float* r = g_r    + row * DD;

    float p0 = p[t], p1 = p[t + 256];
    float r0 = r[t], r1 = r[t + 256];

    float sp = p0 + p1, spp = p0 * p0 + p1 * p1;
    float sr = r0 + r1, srr = r0 * r0 + r1 * r1;

    __shared__ float red[8][4];
#pragma unroll
    for (int off = 16; off; off >>= 1) {
        sp  += __shfl_xor_sync(0xffffffffu, sp,  off);
        spp += __shfl_xor_sync(0xffffffffu, spp, off);
        sr  += __shfl_xor_sync(0xffffffffu, sr,  off);
        srr += __shfl_xor_sync(0xffffffffu, srr, off);
    }
    const int lane = t & 31, w = t >> 5;
    if (lane == 0) { red[w][0] = sp; red[w][1] = spp; red[w][2] = sr; red[w][3] = srr; }
    __syncthreads();
    float Sp = 0.f, Spp = 0.f, Sr = 0.f, Srr = 0.f;
#pragma unroll
    for (int i = 0; i < 8; i++) {
        Sp += red[i][0]; Spp += red[i][1]; Sr += red[i][2]; Srr += red[i][3];
    }

    const float invD = 1.0f / (float)DD;
    const float mup = Sp * invD;
    const float ip  = rsqrtf(Spp * invD - mup * mup + 1e-5f);
    const float mur = Sr * invD;
    const float ir  = rsqrtf(Srr * invD - mur * mur + 1e-5f);

    const float ga0 = gamma[t], ga1 = gamma[t + 256];
    const float be0 = beta[t],  be1 = beta[t + 256];

    const float y0 = (p0 - mup) * ip * ga0 + be0 + (r0 - mur) * ir * ga0 + be0;
    const float y1 = (p1 - mup) * ip * ga1 + be1 + (r1 - mur) * ir * ga1 + be1;

    out[row * DD + t]       = y0 * normcdff(y0);
    out[row * DD + t + 256] = y1 * normcdff(y1);
}

// ---------------------------------------------------------------------------
extern "C" void kernel_launch(void* const* d_in, const int* in_sizes, int n_in,
                              void* d_out, int out_size)
{
    const float* x     = (const float*)d_in[0];
    const float* Wq    = (const float*)d_in[1];
    const float* bq    = (const float*)d_in[2];
    const float* Wk    = (const float*)d_in[3];
    const float* bk    = (const float*)d_in[4];
    const float* Wv    = (const float*)d_in[5];
    const float* bv    = (const float*)d_in[6];
    const float* Wo    = (const float*)d_in[7];
    const float* bo    = (const float*)d_in[8];
    const float* Wr    = (const float*)d_in[9];
    const float* br    = (const float*)d_in[10];
    const float* gamma = (const float*)d_in[11];
    const float* beta  = (const float*)d_in[12];
    float* out = (float*)d_out;

    dim3 gQ(BN == 128 ? 4 : 4, 32, 4);
    k_qkvr<<<gQ, 256>>>(x, Wq, bq, Wk, bk, Wv, bv, Wr, br);

    k_attn<<<MR / 8, 256>>>();

    dim3 gP(4, 32, 1);
    k_proj<<<gP, 256>>>(Wo, bo);

    k_ln_gelu<<<MR, 256>>>(gamma, beta, out);
}

// round 3
// speedup vs baseline: 2.1533x; 2.1533x over previous
#include <cuda_runtime.h>
#include <math.h>
#include <stdint.h>

#define BB   2
#define SS   2048
#define DD   512
#define WW   64
#define MR   (BB*SS)     // 4096 rows

// Scratch (device globals — no allocation allowed)
__device__ float g_q[MR*DD];
__device__ float g_k[MR*DD];
__device__ float g_v[MR*DD];
__device__ float g_r[MR*DD];
__device__ float g_att[MR*DD];
__device__ float g_proj[MR*DD];

__device__ __forceinline__ uint32_t tf32r(float f) {
    uint32_t u; asm("cvt.rna.tf32.f32 %0, %1;" : "=r"(u) : "f"(f)); return u;
}

__device__ __forceinline__ void mma_tf32(float* c, const uint32_t* a, const uint32_t* b) {
    asm("mma.sync.aligned.m16n8k8.row.col.f32.tf32.tf32.f32 "
        "{%0,%1,%2,%3}, {%4,%5,%6,%7}, {%8,%9}, {%0,%1,%2,%3};"
        : "+f"(c[0]), "+f"(c[1]), "+f"(c[2]), "+f"(c[3])
        : "r"(a[0]), "r"(a[1]), "r"(a[2]), "r"(a[3]), "r"(b[0]), "r"(b[1]));
}

// ===========================================================================
// tf32 tensor-core GEMM: C[4096,512] = A[4096,512] @ W[512,512] + bias
// CTA tile 128x128, BK=32, 256 threads (8 warps, warp tile 32x64).
// As[128][36] m-major, Bs[32][132] k-major (pads -> conflict-free frag LDS).
// ===========================================================================
#define SKA 36
#define SKB 132

__device__ __forceinline__ void gemm_mma(const float* __restrict__ A,
                                         const float* __restrict__ W,
                                         const float* __restrict__ bias,
                                         float* __restrict__ C)
{
    __shared__ float As[128 * SKA];
    __shared__ float Bs[32 * SKB];

    const int tid  = threadIdx.x;
    const int lane = tid & 31;
    const int wid  = tid >> 5;
    const int g    = lane >> 2;      // group id 0..7
    const int tg   = lane & 3;       // thread-in-group 0..3
    const int m0   = blockIdx.y * 128;
    const int n0   = blockIdx.x * 128;
    const int wm   = (wid >> 1) * 32;    // warp row offset in tile
    const int wn   = (wid & 1) * 64;     // warp col offset in tile

    // global load mapping (float4 id f = tid + 256*i)
    const int arow = tid >> 3;           // 0..31, +32 per i
    const int acol = (tid & 7) * 4;      // 0..28
    const int brow = tid >> 5;           // 0..7,  +8 per i
    const int bcol = (tid & 31) * 4;     // 0..124

    const float* Ab = A + (m0 + arow) * DD + acol;
    const float* Wb = W + brow * DD + n0 + bcol;

    float4 pa[4], pb[4];
#pragma unroll
    for (int i = 0; i < 4; i++) {
        pa[i] = *(const float4*)(Ab + i * 32 * DD);
        pb[i] = *(const float4*)(Wb + i * 8 * DD);
    }

    float acc[2][8][4];
#pragma unroll
    for (int mt = 0; mt < 2; mt++)
#pragma unroll
        for (int nt = 0; nt < 8; nt++)
#pragma unroll
            for (int q = 0; q < 4; q++) acc[mt][nt][q] = 0.f;

    for (int ch = 0; ch < 16; ch++) {
        __syncthreads();
#pragma unroll
        for (int i = 0; i < 4; i++) {
            uint4 ua;
            ua.x = tf32r(pa[i].x); ua.y = tf32r(pa[i].y);
            ua.z = tf32r(pa[i].z); ua.w = tf32r(pa[i].w);
            *(uint4*)&As[(arow + 32 * i) * SKA + acol] = ua;
            uint4 ub;
            ub.x = tf32r(pb[i].x); ub.y = tf32r(pb[i].y);
            ub.z = tf32r(pb[i].z); ub.w = tf32r(pb[i].w);
            *(uint4*)&Bs[(brow + 8 * i) * SKB + bcol] = ub;
        }
        __syncthreads();

        if (ch < 15) {
            const float* Ab2 = Ab + (ch + 1) * 32;
            const float* Wb2 = Wb + (ch + 1) * 32 * DD;
#pragma unroll
            for (int i = 0; i < 4; i++) {
                pa[i] = *(const float4*)(Ab2 + i * 32 * DD);
                pb[i] = *(const float4*)(Wb2 + i * 8 * DD);
            }
        }

#pragma unroll
        for (int kk = 0; kk < 4; kk++) {
            const int kb = kk * 8;
            uint32_t af[2][4], bf[8][2];
#pragma unroll
            for (int mt = 0; mt < 2; mt++) {
                const int m = wm + mt * 16 + g;
                af[mt][0] = __float_as_uint(As[m * SKA + kb + tg]);
                af[mt][1] = __float_as_uint(As[(m + 8) * SKA + kb + tg]);
                af[mt][2] = __float_as_uint(As[m * SKA + kb + tg + 4]);
                af[mt][3] = __float_as_uint(As[(m + 8) * SKA + kb + tg + 4]);
            }
#pragma unroll
            for (int nt = 0; nt < 8; nt++) {
                const int n = wn + nt * 8 + g;
                bf[nt][0] = __float_as_uint(Bs[(kb + tg) * SKB + n]);
                bf[nt][1] = __float_as_uint(Bs[(kb + tg + 4) * SKB + n]);
            }
#pragma unroll
            for (int mt = 0; mt < 2; mt++)
#pragma unroll
                for (int nt = 0; nt < 8; nt++)
                    mma_tf32(acc[mt][nt], af[mt], bf[nt]);
        }
    }

    // epilogue: bias + direct STG.64 (each 8-lane phase covers 32B runs)
#pragma unroll
    for (int nt = 0; nt < 8; nt++) {
        const int n = n0 + wn + nt * 8 + 2 * tg;
        const float2 bb = *(const float2*)&bias[n];
#pragma unroll
        for (int mt = 0; mt < 2; mt++) {
            const int m = m0 + wm + mt * 16 + g;
            float2 v0 = make_float2(acc[mt][nt][0] + bb.x, acc[mt][nt][1] + bb.y);
            float2 v1 = make_float2(acc[mt][nt][2] + bb.x, acc[mt][nt][3] + bb.y);
            *(float2*)&C[m * DD + n]       = v0;
            *(float2*)&C[(m + 8) * DD + n] = v1;
        }
    }
}

__global__ void __launch_bounds__(256, 2) k_gemm_qkvr(
    const float* __restrict__ x,
    const float* Wq, const float* bq,
    const float* Wk, const float* bk,
    const float* Wv, const float* bv,
    const float* Wr, const float* br)
{
    const float* W; const float* bias; float* C;
    switch (blockIdx.z) {
        case 0:  W = Wq; bias = bq; C = g_q; break;
        case 1:  W = Wk; bias = bk; C = g_k; break;
        case 2:  W = Wv; bias = bv; C = g_v; break;
        default: W = Wr; bias = br; C = g_r; break;
    }
    gemm_mma(x, W, bias, C);
}

__global__ void __launch_bounds__(256, 2) k_gemm_proj(
    const float* __restrict__ Wo, const float* __restrict__ bo)
{
    gemm_mma(g_att, Wo, bo, g_proj);
}

// ===========================================================================
// Local windowed attention: one warp per query, 32 warps (1024 thr) per block
// so neighboring warps hit the same K/V window rows while hot in L1.
// ===========================================================================
__global__ void __launch_bounds__(1024) k_attn()
{
    const int warp = threadIdx.x >> 5;
    const int lane = threadIdx.x & 31;
    const int gq   = blockIdx.x * 32 + warp;
    const int b    = gq / SS;
    const int s    = gq - b * SS;
    const int base = b * SS;

    const float* qrow = g_q + gq * DD;
    float qreg[16];
#pragma unroll
    for (int i = 0; i < 16; i++) qreg[i] = qrow[lane + 32 * i];

    __shared__ float sh[32][WW];
    const int j0 = s - (WW - 1);
    const float scale = 0.044194173824159216f;   // 1/sqrt(512)

    for (int w = 0; w < WW; w++) {
        const int j = j0 + w;
        float part = 0.f;
        if (j >= 0) {
            const float* krow = g_k + (base + j) * DD;
#pragma unroll
            for (int i = 0; i < 16; i++) part += qreg[i] * krow[lane + 32 * i];
        }
#pragma unroll
        for (int off = 16; off; off >>= 1)
            part += __shfl_down_sync(0xffffffffu, part, off);
        if (lane == 0) sh[warp][w] = (j >= 0) ? part * scale : -1e9f;
    }
    __syncwarp();

    float s0 = sh[warp][lane], s1 = sh[warp][lane + 32];
    float mx = fmaxf(s0, s1);
#pragma unroll
    for (int off = 16; off; off >>= 1)
        mx = fmaxf(mx, __shfl_xor_sync(0xffffffffu, mx, off));
    float e0 = expf(s0 - mx), e1 = expf(s1 - mx);
    float sum = e0 + e1;
#pragma unroll
    for (int off = 16; off; off >>= 1)
        sum += __shfl_xor_sync(0xffffffffu, sum, off);
    const float inv = 1.0f / sum;
    sh[warp][lane]      = e0 * inv;
    sh[warp][lane + 32] = e1 * inv;
    __syncwarp();

    float acc[16];
#pragma unroll
    for (int i = 0; i < 16; i++) acc[i] = 0.f;
    for (int w = 0; w < WW; w++) {
        const int j = j0 + w;
        if (j < 0) continue;
        const float p = sh[warp][w];
        const float* vrow = g_v + (base + j) * DD;
#pragma unroll
        for (int i = 0; i < 16; i++) acc[i] += p * vrow[lane + 32 * i];
    }
    float* orow = g_att + gq * DD;
#pragma unroll
    for (int i = 0; i < 16; i++) orow[lane + 32 * i] = acc[i];
}

// ===========================================================================
// Dual LayerNorm + add + exact GELU. One block (256 threads) per row.
// ===========================================================================
__global__ void __launch_bounds__(256) k_ln_gelu(
    const float* __restrict__ gamma, const float* __restrict__ beta,
    float* __restrict__ out)
{
    const int row = blockIdx.x;
    const int t   = threadIdx.x;
    const float* p = g_proj + row * DD;
    const float* r = g_r    + row * DD;

    float p0 = p[t], p1 = p[t + 256];
    float r0 = r[t], r1 = r[t + 256];

    float sp = p0 + p1, spp = p0 * p0 + p1 * p1;
    float sr = r0 + r1, srr = r0 * r0 + r1 * r1;

    __shared__ float red[8][4];
#pragma unroll
    for (int off = 16; off; off >>= 1) {
        sp  += __shfl_xor_sync(0xffffffffu, sp,  off);
        spp += __shfl_xor_sync(0xffffffffu, spp, off);
        sr  += __shfl_xor_sync(0xffffffffu, sr,  off);
        srr += __shfl_xor_sync(0xffffffffu, srr, off);
    }
    const int lane = t & 31, w = t >> 5;
    if (lane == 0) { red[w][0] = sp; red[w][1] = spp; red[w][2] = sr; red[w][3] = srr; }
    __syncthreads();
    float Sp = 0.f, Spp = 0.f, Sr = 0.f, Srr = 0.f;
#pragma unroll
    for (int i = 0; i < 8; i++) {
        Sp += red[i][0]; Spp += red[i][1]; Sr += red[i][2]; Srr += red[i][3];
    }

    const float invD = 1.0f / (float)DD;
    const float mup = Sp * invD;
    const float ip  = rsqrtf(Spp * invD - mup * mup + 1e-5f);
    const float mur = Sr * invD;
    const float ir  = rsqrtf(Srr * invD - mur * mur + 1e-5f);

    const float ga0 = gamma[t], ga1 = gamma[t + 256];
    const float be0 = beta[t],  be1 = beta[t + 256];

    const float y0 = (p0 - mup) * ip * ga0 + be0 + (r0 - mur) * ir * ga0 + be0;
    const float y1 = (p1 - mup) * ip * ga1 + be1 + (r1 - mur) * ir * ga1 + be1;

    out[row * DD + t]       = y0 * normcdff(y0);
    out[row * DD + t + 256] = y1 * normcdff(y1);
}

// ===========================================================================
extern "C" void kernel_launch(void* const* d_in, const int* in_sizes, int n_in,
                              void* d_out, int out_size)
{
    const float* x     = (const float*)d_in[0];
    const float* Wq    = (const float*)d_in[1];
    const float* bq    = (const float*)d_in[2];
    const float* Wk    = (const float*)d_in[3];
    const float* bk    = (const float*)d_in[4];
    const float* Wv    = (const float*)d_in[5];
    const float* bv    = (const float*)d_in[6];
    const float* Wo    = (const float*)d_in[7];
    const float* bo    = (const float*)d_in[8];
    const float* Wr    = (const float*)d_in[9];
    const float* br    = (const float*)d_in[10];
    const float* gamma = (const float*)d_in[11];
    const float* beta  = (const float*)d_in[12];
    float* out = (float*)d_out;

    k_gemm_qkvr<<<dim3(4, 32, 4), 256>>>(x, Wq, bq, Wk, bk, Wv, bv, Wr, br);

    k_attn<<<MR / 32, 1024>>>();

    k_gemm_proj<<<dim3(4, 32, 1), 256>>>(Wo, bo);

    k_ln_gelu<<<MR, 256>>>(gamma, beta, out);
}